// round 5
// baseline (speedup 1.0000x reference)
#include <cuda_runtime.h>

#define BB 16          // batches
#define NN 576         // queries
#define MM 16          // targets
#define DD 81          // classes / emb dim
#define BG 80
#define THR 0.75f
#define NSW 9          // scan warps
#define NST 288        // scan threads

// Per-block partial outputs (fully rewritten each run; no init kernel needed)
__device__ float g_S[BB][DD];
__device__ float g_P[BB][DD];
__device__ int   g_C[BB][DD];
__device__ float g_ce[BB];
__device__ float g_bb[BB];
__device__ float g_gi[BB];
__device__ unsigned g_tick;   // self-wrapping ticket (atomicInc mod BB)

__global__ void __launch_bounds__(NN) k_main(
    const float* __restrict__ emb, const float* __restrict__ cp,
    const float* __restrict__ pb,  const float* __restrict__ tb,
    const int* __restrict__ tl,    const int* __restrict__ mi,
    float* __restrict__ out)
{
    __shared__ float4   sbox[NN];
    __shared__ float    sarea[NN];
    __shared__ int      stc[NN];
    __shared__ unsigned swmin[2][NSW];
    __shared__ float2   sms[NN];        // per-row (max, sumexp)
    __shared__ float    sinv[NN];       // per-row inverse norm
    __shared__ float    sSall[DD];      // tc-independent column sums of max(e-0.5,0)
    __shared__ float    sP[DD];         // sum over rows with lab=c of (1 - e[c])
    __shared__ float    sSneg[DD];      // correction: max(e[lab]-0.5,0) for own label
    __shared__ int      sC[DD];         // label histogram
    __shared__ float    sf[3];          // flbg, flfg, cbg
    __shared__ float    sbb2[2];        // bbox L1 sum, giou sum
    __shared__ int      slast;
    __shared__ float    racc[3];

    const int b    = blockIdx.x;
    const int j    = threadIdx.x;
    const int wid  = j >> 5;
    const int lane = j & 31;

    // ---- phase 0: loads + init ----
    float4 boxj = ((const float4*)pb)[b*NN + j];
    sbox[j]  = boxj;
    sarea[j] = (boxj.z - boxj.x) * (boxj.w - boxj.y);
    stc[j]   = BG;
    if (j < DD) { sSall[j] = 0.f; sP[j] = 0.f; sSneg[j] = 0.f; sC[j] = 0; }
    if (j < 3)  sf[j] = 0.f;
    if (j < 2)  sbb2[j] = 0.f;
    __syncthreads();
    if (j == 0) {
        #pragma unroll
        for (int m = 0; m < MM; m++)
            stc[mi[b*MM + m]] = tl[b*MM + m];
    }
    __syncthreads();

    if (wid < NSW) {
        // ===== SCAN warps 0..8: each owns queries j and j+288, named barrier 1 =====
        const int j2 = j + NST;
        float4 box1 = boxj;
        float4 box2 = sbox[j2];
        float  a1 = sarea[j], a2 = sarea[j2];
        int my1 = stc[j], my2 = stc[j2];
        int cur = 0, par = 0;
        while (true) {
            unsigned c1 = (my1 != BG && j  >= cur) ? (unsigned)j  : (unsigned)NN;
            unsigned c2 = (my2 != BG && j2 >= cur) ? (unsigned)j2 : (unsigned)NN;
            unsigned wm = __reduce_min_sync(0xffffffffu, min(c1, c2));
            if (lane == 0) swmin[par][wid] = wm;
            asm volatile("bar.sync 1, %0;" :: "n"(NST) : "memory");
            unsigned n = NN;
            #pragma unroll
            for (int w = 0; w < NSW; w++) n = min(n, swmin[par][w]);
            if (n >= NN) break;

            int   label = stc[n];
            float an    = sarea[(int)n];
            float4 bn   = sbox[n];
            {
                float lx = fmaxf(bn.x, box1.x), ly = fmaxf(bn.y, box1.y);
                float rx = fminf(bn.z, box1.z), ry = fminf(bn.w, box1.w);
                float w_ = fmaxf(rx - lx, 0.f), h_ = fmaxf(ry - ly, 0.f);
                float inter = w_ * h_;
                if (inter > THR * (an + a1 - inter) && my1 != label) { my1 = label; stc[j] = label; }
            }
            {
                float lx = fmaxf(bn.x, box2.x), ly = fmaxf(bn.y, box2.y);
                float rx = fminf(bn.z, box2.z), ry = fminf(bn.w, box2.w);
                float w_ = fmaxf(rx - lx, 0.f), h_ = fmaxf(ry - ly, 0.f);
                float inter = w_ * h_;
                if (inter > THR * (an + a2 - inter) && my2 != label) { my2 = label; stc[j2] = label; }
            }
            cur = (int)n + 1;
            par ^= 1;
        }
    } else {
        // ===== B1 warps 9..17: tc-independent row stats (runs concurrently) =====
        if (wid == NSW && lane < MM) {
            int idx = mi[b*MM + lane];
            float4 s  = sbox[idx];
            float4 tg = ((const float4*)tb)[b*MM + lane];
            float l1 = fabsf(s.x - tg.x) + fabsf(s.y - tg.y)
                     + fabsf(s.z - tg.z) + fabsf(s.w - tg.w);
            float lx = fmaxf(s.x, tg.x), ly = fmaxf(s.y, tg.y);
            float rx = fminf(s.z, tg.z), ry = fminf(s.w, tg.w);
            float w_ = fmaxf(rx - lx, 0.f), h_ = fmaxf(ry - ly, 0.f);
            float inter = w_ * h_;
            float areas = (s.z - s.x) * (s.w - s.y);
            float areat = (tg.z - tg.x) * (tg.w - tg.y);
            float uni = areas + areat - inter;
            float iou = inter / uni;
            float lx2 = fminf(s.x, tg.x), ly2 = fminf(s.y, tg.y);
            float rx2 = fmaxf(s.z, tg.z), ry2 = fmaxf(s.w, tg.w);
            float ac  = (rx2 - lx2) * (ry2 - ly2);
            atomicAdd(&sbb2[0], l1);
            atomicAdd(&sbb2[1], 1.f - (iou - (ac - uni) / ac));
        }
        const int wb = wid - NSW;           // 0..8, 64 rows each
        const float* cpb = cp  + (size_t)b * NN * DD;
        const float* eb  = emb + (size_t)b * NN * DD;
        float aS0 = 0.f, aS1 = 0.f, aS2 = 0.f;
        #pragma unroll 2
        for (int r = 0; r < 64; r++) {
            int i = wb * 64 + r;
            const float* crow = cpb + (size_t)i * DD;
            const float* erow = eb  + (size_t)i * DD;
            float x0 = crow[lane];
            float x1 = crow[32 + lane];
            float x2 = (lane < 17) ? crow[64 + lane] : -3.0e38f;
            float y0 = erow[lane];
            float y1 = erow[32 + lane];
            float y2 = (lane < 17) ? erow[64 + lane] : 0.f;
            float m = fmaxf(fmaxf(x0, x1), x2);
            #pragma unroll
            for (int o = 16; o; o >>= 1) m = fmaxf(m, __shfl_xor_sync(0xffffffffu, m, o));
            float s = __expf(x0 - m) + __expf(x1 - m) + ((lane < 17) ? __expf(x2 - m) : 0.f);
            float ss = y0*y0 + y1*y1 + y2*y2;
            #pragma unroll
            for (int o = 16; o; o >>= 1) {
                s  += __shfl_xor_sync(0xffffffffu, s,  o);
                ss += __shfl_xor_sync(0xffffffffu, ss, o);
            }
            float inv = rsqrtf(fmaxf(ss, 1e-24f));
            if (lane == 0) { sms[i] = make_float2(m, s); sinv[i] = inv; }
            aS0 += fmaxf(y0 * inv - 0.5f, 0.f);
            aS1 += fmaxf(y1 * inv - 0.5f, 0.f);
            if (lane < 17) aS2 += fmaxf(y2 * inv - 0.5f, 0.f);
        }
        atomicAdd(&sSall[lane],      aS0);
        atomicAdd(&sSall[lane + 32], aS1);
        if (lane < 17) atomicAdd(&sSall[lane + 64], aS2);
    }
    __syncthreads();   // scan + B1 complete; stc/sms/sinv/sSall visible

    // ===== B2: per-row tc-dependent epilogue (all 576 threads) =====
    {
        int t = stc[j];
        float2 ms = sms[j];
        float xt = cp[(size_t)(b*NN + j) * DD + t];
        float e  = emb[(size_t)(b*NN + j) * DD + t] * sinv[j];
        float ce = __logf(ms.y) - (xt - ms.x);
        float p  = __expf(xt - ms.x) / ms.y;     // exp(-ce)
        float fl = (1.f - p) * (1.f - p) * ce;
        bool isbg = (t == BG);
        float flbg = isbg ? 0.1f * fl : 0.f;
        float flfg = isbg ? 0.f : fl;
        float cbg  = isbg ? 1.f : 0.f;
        #pragma unroll
        for (int o = 16; o; o >>= 1) {
            flbg += __shfl_down_sync(0xffffffffu, flbg, o);
            flfg += __shfl_down_sync(0xffffffffu, flfg, o);
            cbg  += __shfl_down_sync(0xffffffffu, cbg,  o);
        }
        if (lane == 0) {
            atomicAdd(&sf[0], flbg);
            atomicAdd(&sf[1], flfg);
            atomicAdd(&sf[2], cbg);
        }
        atomicAdd(&sP[t], 1.f - e);
        atomicAdd(&sSneg[t], fmaxf(e - 0.5f, 0.f));
        atomicAdd(&sC[t], 1);
    }
    __syncthreads();

    // ---- per-batch partial write-out ----
    if (j < DD) {
        g_S[b][j] = sSall[j] - sSneg[j];
        g_P[b][j] = sP[j];
        g_C[b][j] = sC[j];
    }
    if (j == 0) {
        float cb = sf[2];
        g_ce[b] = sf[0] / cb + sf[1] / ((float)NN - cb);
        g_bb[b] = sbb2[0];
        g_gi[b] = sbb2[1];
    }

    // ---- grid sync: last block finalizes ----
    __threadfence();
    __syncthreads();
    if (j == 0) {
        unsigned old = atomicInc(&g_tick, BB - 1u);   // wraps BB-1 -> 0 (self-reset)
        slast = (old == BB - 1u) ? 1 : 0;
    }
    __syncthreads();
    if (!slast) return;
    __threadfence();

    if (j < 3) racc[j] = 0.f;
    __syncthreads();
    if (j < DD) {
        float C = 0.f, P = 0.f, S = 0.f;
        #pragma unroll
        for (int b2 = 0; b2 < BB; b2++) {
            C += (float)g_C[b2][j];
            P += g_P[b2][j];
            S += g_S[b2][j];
        }
        atomicAdd(&racc[0], C * C);
        atomicAdd(&racc[1], C * P);
        atomicAdd(&racc[2], C * S);
    }
    __syncthreads();
    if (j == 0) {
        float ces = 0.f, bbs = 0.f, gis = 0.f;
        #pragma unroll
        for (int b2 = 0; b2 < BB; b2++) { ces += g_ce[b2]; bbs += g_bb[b2]; gis += g_gi[b2]; }
        float pc = racc[0];
        float T  = (float)(BB * NN);
        float nc = T * T - pc;
        out[0] = ces / (float)BB;
        out[1] = (racc[1] / pc + racc[2] / nc) / (float)BB;
        out[2] = bbs / (float)(BB * MM);
        out[3] = gis / (float)(BB * MM);
    }
}

extern "C" void kernel_launch(void* const* d_in, const int* in_sizes, int n_in,
                              void* d_out, int out_size)
{
    const float* emb = (const float*)d_in[0];   // image_embeddings
    const float* cp  = (const float*)d_in[1];   // class_predictions
    const float* pb  = (const float*)d_in[2];   // pred_boxes
    const float* tb  = (const float*)d_in[3];   // target_boxes
    const int*   tl  = (const int*)  d_in[4];   // target_labels
    const int*   mi  = (const int*)  d_in[5];   // match_idx
    float* out = (float*)d_out;

    k_main<<<BB, NN>>>(emb, cp, pb, tb, tl, mi, out);
}

// round 6
// speedup vs baseline: 1.0919x; 1.0919x over previous
#include <cuda_runtime.h>

#define BB 16          // batches
#define NN 576         // queries
#define MM 16          // targets
#define DD 81          // classes / emb dim
#define BG 80
#define THR 0.75f
#define NW 18          // warps per block

// Inter-block staging (fully rewritten each run; flags self-reset via CAS consume)
__device__ float2   g_ms[BB][NN];     // per-row (max, sumexp)
__device__ float    g_inv[BB][NN];    // per-row inverse norm
__device__ float    g_Sall[BB][DD];   // tc-independent column sums
__device__ float    g_S[BB][DD];
__device__ float    g_P[BB][DD];
__device__ int      g_C[BB][DD];
__device__ float    g_ce[BB];
__device__ float    g_bb[BB];
__device__ float    g_gi[BB];
__device__ unsigned g_flag[BB];       // 0 at load; set by stat block, consumed by scan block
__device__ unsigned g_tick;           // self-wrapping ticket over scan blocks

__global__ void __launch_bounds__(NN) k_main(
    const float* __restrict__ emb, const float* __restrict__ cp,
    const float* __restrict__ pb,  const float* __restrict__ tb,
    const int* __restrict__ tl,    const int* __restrict__ mi,
    float* __restrict__ out)
{
    const int j    = threadIdx.x;
    const int wid  = j >> 5;
    const int lane = j & 31;

    if (blockIdx.x >= BB) {
        // ================= STAT BLOCK (batch b): tc-independent work =================
        const int b = blockIdx.x - BB;
        __shared__ float sSall[DD];
        if (j < DD) sSall[j] = 0.f;
        __syncthreads();

        // bbox L1 + GIoU (warp 0)
        if (wid == 0) {
            float l1 = 0.f, gi = 0.f;
            if (lane < MM) {
                int idx = mi[b*MM + lane];
                float4 s  = ((const float4*)pb)[b*NN + idx];
                float4 tg = ((const float4*)tb)[b*MM + lane];
                l1 = fabsf(s.x - tg.x) + fabsf(s.y - tg.y)
                   + fabsf(s.z - tg.z) + fabsf(s.w - tg.w);
                float lx = fmaxf(s.x, tg.x), ly = fmaxf(s.y, tg.y);
                float rx = fminf(s.z, tg.z), ry = fminf(s.w, tg.w);
                float w_ = fmaxf(rx - lx, 0.f), h_ = fmaxf(ry - ly, 0.f);
                float inter = w_ * h_;
                float areas = (s.z - s.x) * (s.w - s.y);
                float areat = (tg.z - tg.x) * (tg.w - tg.y);
                float uni = areas + areat - inter;
                float iou = inter / uni;
                float lx2 = fminf(s.x, tg.x), ly2 = fminf(s.y, tg.y);
                float rx2 = fmaxf(s.z, tg.z), ry2 = fmaxf(s.w, tg.w);
                float ac  = (rx2 - lx2) * (ry2 - ly2);
                gi = 1.f - (iou - (ac - uni) / ac);
            }
            #pragma unroll
            for (int o = 16; o; o >>= 1) {
                l1 += __shfl_down_sync(0xffffffffu, l1, o);
                gi += __shfl_down_sync(0xffffffffu, gi, o);
            }
            if (lane == 0) { g_bb[b] = l1; g_gi[b] = gi; }
        }

        // per-row softmax stats + inverse norms + column sums (warp owns 32 rows)
        const float* cpb = cp  + (size_t)b * NN * DD;
        const float* eb  = emb + (size_t)b * NN * DD;
        float aS0 = 0.f, aS1 = 0.f, aS2 = 0.f;
        #pragma unroll 2
        for (int r = 0; r < 32; r++) {
            int i = wid * 32 + r;
            const float* crow = cpb + (size_t)i * DD;
            const float* erow = eb  + (size_t)i * DD;
            float x0 = crow[lane];
            float x1 = crow[32 + lane];
            float x2 = (lane < 17) ? crow[64 + lane] : -3.0e38f;
            float y0 = erow[lane];
            float y1 = erow[32 + lane];
            float y2 = (lane < 17) ? erow[64 + lane] : 0.f;
            float m = fmaxf(fmaxf(x0, x1), x2);
            #pragma unroll
            for (int o = 16; o; o >>= 1) m = fmaxf(m, __shfl_xor_sync(0xffffffffu, m, o));
            float s = __expf(x0 - m) + __expf(x1 - m) + ((lane < 17) ? __expf(x2 - m) : 0.f);
            float ss = y0*y0 + y1*y1 + y2*y2;
            #pragma unroll
            for (int o = 16; o; o >>= 1) {
                s  += __shfl_xor_sync(0xffffffffu, s,  o);
                ss += __shfl_xor_sync(0xffffffffu, ss, o);
            }
            float inv = rsqrtf(fmaxf(ss, 1e-24f));
            if (lane == 0) { g_ms[b][i] = make_float2(m, s); g_inv[b][i] = inv; }
            aS0 += fmaxf(y0 * inv - 0.5f, 0.f);
            aS1 += fmaxf(y1 * inv - 0.5f, 0.f);
            if (lane < 17) aS2 += fmaxf(y2 * inv - 0.5f, 0.f);
        }
        atomicAdd(&sSall[lane],      aS0);
        atomicAdd(&sSall[lane + 32], aS1);
        if (lane < 17) atomicAdd(&sSall[lane + 64], aS2);
        __syncthreads();
        if (j < DD) g_Sall[b][j] = sSall[j];
        __syncthreads();
        if (j == 0) {
            __threadfence();
            atomicExch(&g_flag[b], 1u);   // publish
        }
        return;
    }

    // ================= SCAN BLOCK (batch b) =================
    const int b = blockIdx.x;
    __shared__ float4   sbox[NN];
    __shared__ float    sarea[NN];
    __shared__ int      stc[NN];
    __shared__ unsigned swmin[2][NW];
    __shared__ float    sP[DD];
    __shared__ float    sSneg[DD];
    __shared__ int      sC[DD];
    __shared__ float    sf[3];
    __shared__ int      slast;
    __shared__ float    racc[3];

    float4 boxj = ((const float4*)pb)[b*NN + j];
    sbox[j]  = boxj;
    float aj = (boxj.z - boxj.x) * (boxj.w - boxj.y);
    sarea[j] = aj;
    stc[j]   = BG;
    if (j < DD) { sP[j] = 0.f; sSneg[j] = 0.f; sC[j] = 0; }
    if (j < 3)  sf[j] = 0.f;
    __syncthreads();
    if (j == 0) {
        #pragma unroll
        for (int m = 0; m < MM; m++)
            stc[mi[b*MM + m]] = tl[b*MM + m];   // last-wins scatter
    }
    __syncthreads();

    int my = stc[j];
    int cur = 0, par = 0;
    while (true) {
        unsigned cand = (my != BG && j >= cur) ? (unsigned)j : (unsigned)NN;
        unsigned wm = __reduce_min_sync(0xffffffffu, cand);
        if (lane == 0) swmin[par][wid] = wm;
        __syncthreads();
        unsigned v = (lane < NW) ? swmin[par][lane] : (unsigned)NN;
        unsigned n = __reduce_min_sync(0xffffffffu, v);
        if (n >= NN) break;

        int label = stc[n];
        if (my != label) {                     // skip IoU when relabel is a no-op
            float4 bn = sbox[n];
            float an  = sarea[n];
            float lx = fmaxf(bn.x, boxj.x), ly = fmaxf(bn.y, boxj.y);
            float rx = fminf(bn.z, boxj.z), ry = fminf(bn.w, boxj.w);
            float w_ = fmaxf(rx - lx, 0.f), h_ = fmaxf(ry - ly, 0.f);
            float inter = w_ * h_;
            if (inter > THR * (an + aj - inter)) { my = label; stc[j] = label; }
        }
        cur = (int)n + 1;
        par ^= 1;
    }
    __syncthreads();   // final stc writes visible

    // acquire stats from the paired stat block (usually already done)
    if (j == 0) {
        while (atomicCAS(&g_flag[b], 1u, 0u) != 1u) { __nanosleep(64); }
        __threadfence();
    }
    __syncthreads();

    // ===== B2: per-row tc-dependent epilogue =====
    {
        int t = stc[j];
        float2 ms = g_ms[b][j];
        float inv = g_inv[b][j];
        float xt = cp[(size_t)(b*NN + j) * DD + t];
        float e  = emb[(size_t)(b*NN + j) * DD + t] * inv;
        float ce = __logf(ms.y) - (xt - ms.x);
        float p  = __expf(xt - ms.x) / ms.y;     // exp(-ce)
        float fl = (1.f - p) * (1.f - p) * ce;
        bool isbg = (t == BG);
        float flbg = isbg ? 0.1f * fl : 0.f;
        float flfg = isbg ? 0.f : fl;
        float cbg  = isbg ? 1.f : 0.f;
        #pragma unroll
        for (int o = 16; o; o >>= 1) {
            flbg += __shfl_down_sync(0xffffffffu, flbg, o);
            flfg += __shfl_down_sync(0xffffffffu, flfg, o);
            cbg  += __shfl_down_sync(0xffffffffu, cbg,  o);
        }
        if (lane == 0) {
            atomicAdd(&sf[0], flbg);
            atomicAdd(&sf[1], flfg);
            atomicAdd(&sf[2], cbg);
        }
        atomicAdd(&sP[t], 1.f - e);
        atomicAdd(&sSneg[t], fmaxf(e - 0.5f, 0.f));
        atomicAdd(&sC[t], 1);
    }
    __syncthreads();

    // per-batch partials
    if (j < DD) {
        g_S[b][j] = g_Sall[b][j] - sSneg[j];
        g_P[b][j] = sP[j];
        g_C[b][j] = sC[j];
    }
    if (j == 0) {
        float cb = sf[2];
        g_ce[b] = sf[0] / cb + sf[1] / ((float)NN - cb);
    }

    // last scan block finalizes
    __threadfence();
    __syncthreads();
    if (j == 0) {
        unsigned old = atomicInc(&g_tick, BB - 1u);   // wraps BB-1 -> 0
        slast = (old == BB - 1u) ? 1 : 0;
    }
    __syncthreads();
    if (!slast) return;
    __threadfence();

    if (j < 3) racc[j] = 0.f;
    __syncthreads();
    if (j < DD) {
        float C = 0.f, P = 0.f, S = 0.f;
        #pragma unroll
        for (int b2 = 0; b2 < BB; b2++) {
            C += (float)g_C[b2][j];
            P += g_P[b2][j];
            S += g_S[b2][j];
        }
        atomicAdd(&racc[0], C * C);
        atomicAdd(&racc[1], C * P);
        atomicAdd(&racc[2], C * S);
    }
    __syncthreads();
    if (j == 0) {
        float ces = 0.f, bbs = 0.f, gis = 0.f;
        #pragma unroll
        for (int b2 = 0; b2 < BB; b2++) { ces += g_ce[b2]; bbs += g_bb[b2]; gis += g_gi[b2]; }
        float pc = racc[0];
        float T  = (float)(BB * NN);
        float nc = T * T - pc;
        out[0] = ces / (float)BB;
        out[1] = (racc[1] / pc + racc[2] / nc) / (float)BB;
        out[2] = bbs / (float)(BB * MM);
        out[3] = gis / (float)(BB * MM);
    }
}

extern "C" void kernel_launch(void* const* d_in, const int* in_sizes, int n_in,
                              void* d_out, int out_size)
{
    const float* emb = (const float*)d_in[0];   // image_embeddings
    const float* cp  = (const float*)d_in[1];   // class_predictions
    const float* pb  = (const float*)d_in[2];   // pred_boxes
    const float* tb  = (const float*)d_in[3];   // target_boxes
    const int*   tl  = (const int*)  d_in[4];   // target_labels
    const int*   mi  = (const int*)  d_in[5];   // match_idx
    float* out = (float*)d_out;

    k_main<<<2*BB, NN>>>(emb, cp, pb, tb, tl, mi, out);
}